// round 5
// baseline (speedup 1.0000x reference)
#include <cuda_runtime.h>
#include <math.h>

#define NN   50000
#define EE   1600000
#define ET   (EE + NN)
#define INC  256
#define HC   128
#define H1   4
#define C1   32
#define BN_EPS 1e-5f
#define NB   196            // ceil(NN/256)

typedef unsigned long long ull;

// ---------------- scratch ----------------
__device__ float g_xs1 [NN * HC];
__device__ float g_out1[NN * HC];
__device__ float g_xs2 [NN * C1];
__device__ float g_als1[NN * H1];
__device__ float g_ald1[NN * H1];
__device__ float g_als2[NN];
__device__ float g_ald2[NN];
__device__ int   g_deg   [NN];
__device__ int   g_rowptr[NN + 1];
__device__ int   g_cursor[NN];
__device__ int   g_bsum[NB];
__device__ int   g_boff[NB];
__device__ int2  g_pm[ET];          // (src, edge_attr bits), dst-CSR order
__device__ float g_partial[512];
__device__ float g_mean;
__device__ float g_k1v[H1];
__device__ float g_k2;

// ---------------- f32x2 helpers ----------------
__device__ __forceinline__ void fma2(ull &d, ull a, ull b) {
    asm("fma.rn.f32x2 %0, %1, %2, %0;" : "+l"(d) : "l"(a), "l"(b));
}
__device__ __forceinline__ ull pack2(float x, float y) {
    ull r; asm("mov.b64 %0, {%1, %2};" : "=l"(r) : "f"(x), "f"(y)); return r;
}
__device__ __forceinline__ float2 unpack2(ull v) {
    float2 f; asm("mov.b64 {%0, %1}, %2;" : "=f"(f.x), "=f"(f.y) : "l"(v)); return f;
}

__device__ __forceinline__ float leaky(float x) { return x > 0.f ? x : 0.2f * x; }
__device__ __forceinline__ float elu(float x)   { return x > 0.f ? x : expm1f(x); }
__device__ __forceinline__ float wexp(float x)  { return __expf(fminf(x, 80.f)); }

// ---------------- CSR build ----------------
__global__ void init_deg_kernel() {
    int i = blockIdx.x * blockDim.x + threadIdx.x;
    if (i < NN) g_deg[i] = 1;   // self loop
}

__global__ void hist_mean_kernel(const int* __restrict__ ei, const float* __restrict__ ea) {
    __shared__ float s[256];
    float v = 0.f;
    for (int e = blockIdx.x * blockDim.x + threadIdx.x; e < EE; e += gridDim.x * blockDim.x) {
        atomicAdd(&g_deg[ei[EE + e]], 1);
        v += ea[e];
    }
    s[threadIdx.x] = v; __syncthreads();
    for (int o = 128; o > 0; o >>= 1) {
        if (threadIdx.x < o) s[threadIdx.x] += s[threadIdx.x + o];
        __syncthreads();
    }
    if (threadIdx.x == 0) g_partial[blockIdx.x] = s[0];
}

__global__ void mean_fin_kernel(const float* __restrict__ We1, const float* __restrict__ ae1,
                                const float* __restrict__ We2, const float* __restrict__ ae2) {
    __shared__ float s[512];
    int t = threadIdx.x;
    s[t] = g_partial[t]; __syncthreads();
    for (int o = 256; o > 0; o >>= 1) {
        if (t < o) s[t] += s[t + o];
        __syncthreads();
    }
    if (t == 0) g_mean = s[0] / (float)EE;
    if (t < H1) {
        float k = 0.f;
        for (int c = 0; c < C1; c++) k += We1[t * C1 + c] * ae1[t * C1 + c];
        g_k1v[t] = k;
    }
    if (t == H1) {
        float k = 0.f;
        for (int c = 0; c < C1; c++) k += We2[c] * ae2[c];
        g_k2 = k;
    }
}

// ---- 3-phase parallel scan ----
__global__ void scan_part_kernel() {
    __shared__ int s[256];
    int t = threadIdx.x, b = blockIdx.x;
    int i = b * 256 + t;
    int v = (i < NN) ? g_deg[i] : 0;
    s[t] = v; __syncthreads();
    for (int o = 128; o > 0; o >>= 1) {
        if (t < o) s[t] += s[t + o];
        __syncthreads();
    }
    if (t == 0) g_bsum[b] = s[0];
}

__global__ void scan_mid_kernel() {
    __shared__ int s[256];
    int t = threadIdx.x;
    int v = (t < NB) ? g_bsum[t] : 0;
    s[t] = v; __syncthreads();
    for (int o = 1; o < 256; o <<= 1) {
        int u = (t >= o) ? s[t - o] : 0;
        __syncthreads();
        s[t] += u;
        __syncthreads();
    }
    if (t < NB) g_boff[t] = s[t] - v;   // exclusive
}

__global__ void scan_fin_kernel() {
    __shared__ int s[256];
    int t = threadIdx.x, b = blockIdx.x;
    int i = b * 256 + t;
    int v = (i < NN) ? g_deg[i] : 0;
    s[t] = v; __syncthreads();
    for (int o = 1; o < 256; o <<= 1) {
        int u = (t >= o) ? s[t - o] : 0;
        __syncthreads();
        s[t] += u;
        __syncthreads();
    }
    int excl = s[t] - v + g_boff[b];
    if (i < NN) { g_rowptr[i] = excl; g_cursor[i] = excl; }
    if (b == 0 && t == 0) g_rowptr[NN] = ET;
}

// ---------------- GEMM1: [NN,256] @ [256,128] with f32x2 ----------------
__global__ void sgemm1_kernel(const float* __restrict__ A, const float* __restrict__ B) {
    const int K = INC, Nn = HC;
    __shared__ float As[8][128];
    __shared__ float Bs[8][128];
    int tid  = threadIdx.x;
    int brow = blockIdx.x;
    int trow = (tid / 16) * 8;
    int tcol = (tid % 16) * 8;
    int rowA = tid / 2,  colA = (tid % 2) * 4;
    int rowB = tid / 32, colB = (tid % 32) * 4;
    int ag = brow * 128 + rowA;

    ull acc2[4][8];
#pragma unroll
    for (int p = 0; p < 4; p++)
#pragma unroll
        for (int j = 0; j < 8; j++) acc2[p][j] = 0ULL;

    for (int k0 = 0; k0 < K; k0 += 8) {
        float4 av = make_float4(0.f, 0.f, 0.f, 0.f);
        if (ag < NN) av = *(const float4*)(A + (size_t)ag * K + k0 + colA);
        As[colA + 0][rowA] = av.x;
        As[colA + 1][rowA] = av.y;
        As[colA + 2][rowA] = av.z;
        As[colA + 3][rowA] = av.w;
        float4 bv = *(const float4*)(B + (size_t)(k0 + rowB) * Nn + colB);
        *(float4*)(&Bs[rowB][colB]) = bv;
        __syncthreads();
#pragma unroll
        for (int kk = 0; kk < 8; kk++) {
            ull ar2[4];
#pragma unroll
            for (int p = 0; p < 4; p++) {
                float2 a2 = *(const float2*)(&As[kk][trow + 2 * p]);
                ar2[p] = pack2(a2.x, a2.y);
            }
            ull br2[8];
#pragma unroll
            for (int j = 0; j < 8; j++) {
                float b = Bs[kk][tcol + j];
                br2[j] = pack2(b, b);
            }
#pragma unroll
            for (int p = 0; p < 4; p++)
#pragma unroll
                for (int j = 0; j < 8; j++) fma2(acc2[p][j], ar2[p], br2[j]);
        }
        __syncthreads();
    }
#pragma unroll
    for (int p = 0; p < 4; p++) {
        float c0[8], c1[8];
#pragma unroll
        for (int j = 0; j < 8; j++) {
            float2 v = unpack2(acc2[p][j]);
            c0[j] = v.x; c1[j] = v.y;
        }
        int r = brow * 128 + trow + 2 * p;
        if (r < NN) {
            float* cp = g_xs1 + (size_t)r * Nn + tcol;
            *(float4*)(cp)     = make_float4(c0[0], c0[1], c0[2], c0[3]);
            *(float4*)(cp + 4) = make_float4(c0[4], c0[5], c0[6], c0[7]);
        }
        if (r + 1 < NN) {
            float* cp = g_xs1 + (size_t)(r + 1) * Nn + tcol;
            *(float4*)(cp)     = make_float4(c1[0], c1[1], c1[2], c1[3]);
            *(float4*)(cp + 4) = make_float4(c1[4], c1[5], c1[6], c1[7]);
        }
    }
}

// ---------------- attention coefficients (layer 1), float4 ----------------
__global__ void al1_kernel(const float* __restrict__ as1, const float* __restrict__ ad1) {
    int idx = blockIdx.x * blockDim.x + threadIdx.x;
    if (idx >= NN * H1) return;
    int n = idx >> 2, h = idx & 3;
    const float4* xp = (const float4*)(g_xs1 + (size_t)n * HC + h * C1);
    const float4* ap = (const float4*)(as1 + h * C1);
    const float4* dp = (const float4*)(ad1 + h * C1);
    float s = 0.f, d = 0.f;
#pragma unroll
    for (int c = 0; c < 8; c++) {
        float4 v = xp[c], a = ap[c], b = dp[c];
        s += v.x * a.x + v.y * a.y + v.z * a.z + v.w * a.w;
        d += v.x * b.x + v.y * b.y + v.z * b.z + v.w * b.w;
    }
    g_als1[idx] = s;
    g_ald1[idx] = d;
}

// ---------------- scatter: build dst-CSR of (src, ea) pairs ----------------
__global__ void scatter_kernel(const int* __restrict__ ei, const float* __restrict__ ea) {
    float mn = g_mean;
    for (int idx = blockIdx.x * blockDim.x + threadIdx.x; idx < ET; idx += gridDim.x * blockDim.x) {
        int srcn, dstn; float eav;
        if (idx < EE) {
            srcn = ei[idx];
            dstn = ei[EE + idx];
            eav  = ea[idx];
        } else {
            srcn = dstn = idx - EE;
            eav  = mn;
        }
        int slot = atomicAdd(&g_cursor[dstn], 1);
        g_pm[slot] = make_int2(srcn, __float_as_int(eav));
    }
}

// ---------------- agg1: warp/node, inline softmax weights, fused bias+bn+elu ----
__global__ void agg1_kernel(const float* __restrict__ b1, const float* __restrict__ g1,
                            const float* __restrict__ be1) {
    int n    = (blockIdx.x * blockDim.x + threadIdx.x) >> 5;
    int lane = threadIdx.x & 31;
    if (n >= NN) return;
    int beg = g_rowptr[n], end = g_rowptr[n + 1];
    float4 ald = *(const float4*)(g_ald1 + n * 4);            // uniform
    float k0 = g_k1v[0], k1 = g_k1v[1], k2 = g_k1v[2], k3 = g_k1v[3];

    float acc0 = 0.f, acc1 = 0.f, acc2 = 0.f, acc3 = 0.f;
    float den0 = 0.f, den1 = 0.f, den2 = 0.f, den3 = 0.f;
    int e = beg;
    for (; e + 2 <= end; e += 2) {
        int2 pA = g_pm[e], pB = g_pm[e + 1];
        float4 sA = *(const float4*)(g_als1 + pA.x * 4);
        float4 sB = *(const float4*)(g_als1 + pB.x * 4);
        const float* xA = g_xs1 + (size_t)pA.x * HC + lane;
        const float* xB = g_xs1 + (size_t)pB.x * HC + lane;
        float a0 = xA[0], a1 = xA[32], a2 = xA[64], a3 = xA[96];
        float c0 = xB[0], c1 = xB[32], c2 = xB[64], c3 = xB[96];
        float eA = __int_as_float(pA.y), eB = __int_as_float(pB.y);
        float wA0 = wexp(leaky(sA.x + ald.x + k0 * eA));
        float wA1 = wexp(leaky(sA.y + ald.y + k1 * eA));
        float wA2 = wexp(leaky(sA.z + ald.z + k2 * eA));
        float wA3 = wexp(leaky(sA.w + ald.w + k3 * eA));
        float wB0 = wexp(leaky(sB.x + ald.x + k0 * eB));
        float wB1 = wexp(leaky(sB.y + ald.y + k1 * eB));
        float wB2 = wexp(leaky(sB.z + ald.z + k2 * eB));
        float wB3 = wexp(leaky(sB.w + ald.w + k3 * eB));
        acc0 += wA0 * a0 + wB0 * c0;  den0 += wA0 + wB0;
        acc1 += wA1 * a1 + wB1 * c1;  den1 += wA1 + wB1;
        acc2 += wA2 * a2 + wB2 * c2;  den2 += wA2 + wB2;
        acc3 += wA3 * a3 + wB3 * c3;  den3 += wA3 + wB3;
    }
    for (; e < end; ++e) {
        int2 p = g_pm[e];
        float4 s = *(const float4*)(g_als1 + p.x * 4);
        const float* xr = g_xs1 + (size_t)p.x * HC + lane;
        float ev = __int_as_float(p.y);
        float w0 = wexp(leaky(s.x + ald.x + k0 * ev));
        float w1 = wexp(leaky(s.y + ald.y + k1 * ev));
        float w2 = wexp(leaky(s.z + ald.z + k2 * ev));
        float w3 = wexp(leaky(s.w + ald.w + k3 * ev));
        acc0 += w0 * xr[0];  den0 += w0;
        acc1 += w1 * xr[32]; den1 += w1;
        acc2 += w2 * xr[64]; den2 += w2;
        acc3 += w3 * xr[96]; den3 += w3;
    }
    float inv = rsqrtf(1.f + BN_EPS);
    float* op = g_out1 + (size_t)n * HC + lane;
#pragma unroll
    for (int h = 0; h < 4; h++) {
        float a = (h == 0) ? acc0 : (h == 1) ? acc1 : (h == 2) ? acc2 : acc3;
        float d = (h == 0) ? den0 : (h == 1) ? den1 : (h == 2) ? den2 : den3;
        int c = h * 32 + lane;
        float v = a / (d + 1e-16f) + b1[c];
        v = v * (g1[c] * inv) + be1[c];
        op[h * 32] = elu(v);
    }
}

// ---------------- GEMM2 + fused al2 ----------------
__global__ void gemm2_kernel(const float* __restrict__ W2, const float* __restrict__ as2,
                             const float* __restrict__ ad2) {
    __shared__ float Ws[HC * C1];
    for (int i = threadIdx.x; i < HC * C1; i += blockDim.x) Ws[i] = W2[i];
    __syncthreads();
    int node = blockIdx.x * 8 + threadIdx.x / 32;
    int lane = threadIdx.x & 31;
    if (node >= NN) return;
    const float* row = g_out1 + (size_t)node * HC;
    float s = 0.f;
#pragma unroll 8
    for (int k = 0; k < HC; k++) s += row[k] * Ws[k * C1 + lane];
    g_xs2[(size_t)node * C1 + lane] = s;

    float ps = s * as2[lane];
    float pd = s * ad2[lane];
#pragma unroll
    for (int off = 16; off > 0; off >>= 1) {
        ps += __shfl_xor_sync(0xffffffffu, ps, off);
        pd += __shfl_xor_sync(0xffffffffu, pd, off);
    }
    if (lane == 0) { g_als2[node] = ps; g_ald2[node] = pd; }
}

// ---------------- agg2: warp/node, inline weights, fused bn+elu + heads ----------
__global__ void agg2_heads_kernel(const float* __restrict__ b2, const float* __restrict__ g2,
                                  const float* __restrict__ be2,
                                  const float* __restrict__ Wc1, const float* __restrict__ bc1,
                                  const float* __restrict__ Wc2, const float* __restrict__ bc2,
                                  const float* __restrict__ Wr1, const float* __restrict__ br1,
                                  const float* __restrict__ Wr2, const float* __restrict__ br2,
                                  float* __restrict__ out) {
    __shared__ float sWc1[C1 * 16], sWr1[C1 * 16];
    __shared__ float sWc2[32], sWr2[16];
    __shared__ float sbc1[16], sbr1[16], sbc2[2], sbr2v[1];
    __shared__ float sh[8][32];
    int t = threadIdx.x;
    for (int i = t; i < C1 * 16; i += blockDim.x) { sWc1[i] = Wc1[i]; sWr1[i] = Wr1[i]; }
    if (t < 32) sWc2[t] = Wc2[t];
    if (t < 16) { sWr2[t] = Wr2[t]; sbc1[t] = bc1[t]; sbr1[t] = br1[t]; }
    if (t < 2)  sbc2[t] = bc2[t];
    if (t == 32) sbr2v[0] = br2[0];
    __syncthreads();

    int wi   = t >> 5;
    int lane = t & 31;
    int n    = blockIdx.x * 8 + wi;
    if (n >= NN) return;
    int beg = g_rowptr[n], end = g_rowptr[n + 1];
    float ald = g_ald2[n];                    // uniform
    float k2  = g_k2;

    float den = 0.f, acc = 0.f;
    int e = beg;
    for (; e + 2 <= end; e += 2) {
        int2 pA = g_pm[e], pB = g_pm[e + 1];
        float sA = g_als2[pA.x], sB = g_als2[pB.x];
        float xA = g_xs2[(size_t)pA.x * C1 + lane];
        float xB = g_xs2[(size_t)pB.x * C1 + lane];
        float wA = wexp(leaky(sA + ald + k2 * __int_as_float(pA.y)));
        float wB = wexp(leaky(sB + ald + k2 * __int_as_float(pB.y)));
        acc += wA * xA + wB * xB;
        den += wA + wB;
    }
    for (; e < end; ++e) {
        int2 p = g_pm[e];
        float w = wexp(leaky(g_als2[p.x] + ald + k2 * __int_as_float(p.y)));
        acc += w * g_xs2[(size_t)p.x * C1 + lane];
        den += w;
    }
    float v = acc / (den + 1e-16f) + b2[lane];
    v = v * (g2[lane] * rsqrtf(1.f + BN_EPS)) + be2[lane];
    float h = elu(v);
    out[3 * NN + (size_t)n * C1 + lane] = h;
    sh[wi][lane] = h;
    __syncwarp();

    // heads: lanes 0-15 classifier hidden units, lanes 16-31 regressor hidden units
    int j = lane & 15;
    const float* W = (lane < 16) ? sWc1 : sWr1;
    float tt = (lane < 16) ? sbc1[j] : sbr1[j];
#pragma unroll
    for (int c = 0; c < C1; c++) tt += sh[wi][c] * W[c * 16 + j];
    tt = fmaxf(tt, 0.f);
    float pa = (lane < 16) ? tt * sWc2[j * 2 + 0] : tt * sWr2[j];
    float pb = (lane < 16) ? tt * sWc2[j * 2 + 1] : 0.f;
#pragma unroll
    for (int off = 8; off > 0; off >>= 1) {
        pa += __shfl_xor_sync(0xffffffffu, pa, off);
        pb += __shfl_xor_sync(0xffffffffu, pb, off);
    }
    if (lane == 0) {
        out[(size_t)n * 2 + 0] = pa + sbc2[0];
        out[(size_t)n * 2 + 1] = pb + sbc2[1];
    }
    if (lane == 16) {
        out[2 * NN + n] = pa + sbr2v[0];
    }
}

// ---------------- launch ----------------
extern "C" void kernel_launch(void* const* d_in, const int* in_sizes, int n_in,
                              void* d_out, int out_size) {
    const float* x   = (const float*)d_in[0];
    const int*   ei  = (const int*)d_in[1];     // int32 (JAX x64 disabled)
    const float* ea  = (const float*)d_in[2];
    const float* W1  = (const float*)d_in[3];
    const float* as1 = (const float*)d_in[4];
    const float* ad1 = (const float*)d_in[5];
    const float* We1 = (const float*)d_in[6];
    const float* ae1 = (const float*)d_in[7];
    const float* b1  = (const float*)d_in[8];
    const float* g1  = (const float*)d_in[9];
    const float* be1 = (const float*)d_in[10];
    const float* W2  = (const float*)d_in[11];
    const float* as2 = (const float*)d_in[12];
    const float* ad2 = (const float*)d_in[13];
    const float* We2 = (const float*)d_in[14];
    const float* ae2 = (const float*)d_in[15];
    const float* b2  = (const float*)d_in[16];
    const float* g2  = (const float*)d_in[17];
    const float* be2 = (const float*)d_in[18];
    const float* Wc1 = (const float*)d_in[19];
    const float* bc1 = (const float*)d_in[20];
    const float* Wc2 = (const float*)d_in[21];
    const float* bc2 = (const float*)d_in[22];
    const float* Wr1 = (const float*)d_in[23];
    const float* br1 = (const float*)d_in[24];
    const float* Wr2 = (const float*)d_in[25];
    const float* br2 = (const float*)d_in[26];
    float* out = (float*)d_out;

    init_deg_kernel<<<(NN + 255) / 256, 256>>>();                 // 0
    hist_mean_kernel<<<512, 256>>>(ei, ea);                        // 1
    mean_fin_kernel<<<1, 512>>>(We1, ae1, We2, ae2);               // 2
    sgemm1_kernel<<<(NN + 127) / 128, 256>>>(x, W1);               // 3 <- profiled slot
    al1_kernel<<<(NN * H1 + 255) / 256, 256>>>(as1, ad1);          // 4
    scan_part_kernel<<<NB, 256>>>();                               // 5
    scan_mid_kernel<<<1, 256>>>();                                 // 6
    scan_fin_kernel<<<NB, 256>>>();                                // 7
    scatter_kernel<<<2048, 256>>>(ei, ea);                         // 8
    agg1_kernel<<<(NN + 7) / 8, 256>>>(b1, g1, be1);               // 9
    gemm2_kernel<<<(NN + 7) / 8, 256>>>(W2, as2, ad2);             // 10
    agg2_heads_kernel<<<(NN + 7) / 8, 256>>>(b2, g2, be2,
        Wc1, bc1, Wc2, bc2, Wr1, br1, Wr2, br2, out);              // 11
}